// round 12
// baseline (speedup 1.0000x reference)
#include <cuda_runtime.h>
#include <math.h>
#include <stdint.h>

#define B_SZ 16384
#define D_SZ 4096
#define H_SZ 128
#define E_SZ 64
#define K_TOP 8

// Pre-split W1 (tf32 hi/lo bit patterns), [k][n] layout, 2 MB each.
__device__ uint32_t g_bh[D_SZ * H_SZ];
__device__ uint32_t g_bl[D_SZ * H_SZ];

__device__ __forceinline__ uint32_t f2tf32(float x) {
    uint32_t r;
    asm("cvt.rna.tf32.f32 %0, %1;" : "=r"(r) : "f"(x));
    return r;
}
__device__ __forceinline__ void split_tf32(float x, uint32_t& hi, uint32_t& lo) {
    hi = f2tf32(x);
    lo = f2tf32(x - __uint_as_float(hi));
}

#define MMA_TF32(C, A0, A1, A2, A3, B0, B1)                                   \
    asm volatile(                                                             \
        "mma.sync.aligned.m16n8k8.row.col.f32.tf32.tf32.f32 "                 \
        "{%0,%1,%2,%3}, {%4,%5,%6,%7}, {%8,%9}, {%0,%1,%2,%3};"               \
        : "+f"(C[0]), "+f"(C[1]), "+f"(C[2]), "+f"(C[3])                      \
        : "r"(A0), "r"(A1), "r"(A2), "r"(A3), "r"(B0), "r"(B1))

// ---------------------------------------------------------------------------
// Prep: split W1[0:4096][0:128] into tf32 hi/lo, same [k][n] layout.
// ---------------------------------------------------------------------------
__global__ __launch_bounds__(256)
void prep_b_kernel(const float* __restrict__ W1) {
    int idx = (blockIdx.x * 256 + threadIdx.x) * 4;     // float4 granularity
    float4 v = *(const float4*)&W1[idx];
    uint4 h4, l4;
    split_tf32(v.x, h4.x, l4.x); split_tf32(v.y, h4.y, l4.y);
    split_tf32(v.z, h4.z, l4.z); split_tf32(v.w, h4.w, l4.w);
    *(uint4*)&g_bh[idx] = h4;
    *(uint4*)&g_bl[idx] = l4;
}

// ---------------------------------------------------------------------------
// Fused kernel: h = silu(features @ W1 + b1) [3xTF32 mma.sync, 2-stage pipe]
// then logits = h @ W2 + b2, top-8, softmax, scatter [in-block epilogue].
// BM=128, BN=128(H), BK=32. 512 threads = 16 warps (4m x 4n), warp tile 32x32.
// B tiles stream pre-split from g_bh/g_bl (no cvt in mainloop).
// ---------------------------------------------------------------------------
#define BK 32
#define AS_STRIDE 36   // bank(4r + 8ks + tg): frag loads conflict-free
#define BS_STRIDE 136  // bank(8tg + g): frag loads conflict-free

#define A_STG   (128 * AS_STRIDE)        // 4608 u32
#define B_STG   (BK * BS_STRIDE)         // 4352 u32
#define STG     (2 * A_STG + 2 * B_STG)  // 17920 u32 per stage
#define OFF_AH(s) ((s) * STG + 0)
#define OFF_AL(s) ((s) * STG + A_STG)
#define OFF_BH(s) ((s) * STG + 2 * A_STG)
#define OFF_BL(s) ((s) * STG + 2 * A_STG + B_STG)
#define SMEM_U32  (2 * STG)              // 35840 u32 = 143360 bytes

// epilogue overlays: hs (128 x HS_STRIDE f32) on stage 0, ws2 pairs on stage 1
#define HS_STRIDE 132                    // 128*132 = 16896 u32 <= STG

__global__ __launch_bounds__(512)
void fused_router_kernel(const float* __restrict__ A,     // (B, D)
                         const float* __restrict__ W1,    // (D+3, H)
                         const float* __restrict__ b1,    // (H)
                         const float* __restrict__ stepp, // (1)
                         const float* __restrict__ hn,    // (B)
                         const float* __restrict__ conf,  // (B)
                         const float* __restrict__ W2,    // (H, E)
                         const float* __restrict__ b2,    // (E)
                         float* __restrict__ out)
{
    extern __shared__ uint32_t smem[];

    const int tid  = threadIdx.x;
    const int lane = tid & 31;
    const int w    = tid >> 5;
    const int wm   = (w & 3) * 32;   // 4 warps in m
    const int wn   = (w >> 2) * 32;  // 4 warps in n
    const int g    = lane >> 2;
    const int tg   = lane & 3;
    const int m0   = blockIdx.x * 128;

    float acc[2][4][4];
    float sum[2][4][4];
#pragma unroll
    for (int mi = 0; mi < 2; ++mi)
#pragma unroll
        for (int ni = 0; ni < 4; ++ni)
#pragma unroll
            for (int c = 0; c < 4; ++c) { acc[mi][ni][c] = 0.0f; sum[mi][ni][c] = 0.0f; }

    // Per iteration: A tile 128x32 = 1024 float4 (2/thread): f=i*512+tid,
    // arow=f>>3, ak=(f&7)*4. B tile 32x128 = 1024 u32x4 (2/thread x hi/lo):
    // brow=f>>5, bc=(f&31)*4.
    float4 pa[2];
    uint4  pbh[2], pbl[2];
#pragma unroll
    for (int i = 0; i < 2; ++i) {
        int f = i * 512 + tid;
        pa[i]  = *(const float4*)&A[(size_t)(m0 + (f >> 3)) * D_SZ + (f & 7) * 4];
        pbh[i] = *(const uint4*)&g_bh[(size_t)(f >> 5) * H_SZ + (f & 31) * 4];
        pbl[i] = *(const uint4*)&g_bl[(size_t)(f >> 5) * H_SZ + (f & 31) * 4];
    }

    // prologue: fill stage 0
#pragma unroll
    for (int i = 0; i < 2; ++i) {
        int f = i * 512 + tid;
        uint4 h4, l4;
        split_tf32(pa[i].x, h4.x, l4.x); split_tf32(pa[i].y, h4.y, l4.y);
        split_tf32(pa[i].z, h4.z, l4.z); split_tf32(pa[i].w, h4.w, l4.w);
        int ao = (f >> 3) * AS_STRIDE + (f & 7) * 4;
        *(uint4*)&smem[OFF_AH(0) + ao] = h4;
        *(uint4*)&smem[OFF_AL(0) + ao] = l4;
        int bo = (f >> 5) * BS_STRIDE + (f & 31) * 4;
        *(uint4*)&smem[OFF_BH(0) + bo] = pbh[i];
        *(uint4*)&smem[OFF_BL(0) + bo] = pbl[i];
    }

    const int NIT = D_SZ / BK;   // 128
    for (int it = 0; it < NIT; ++it) {
        __syncthreads();
        const int cur = it & 1;
        const bool pre = (it + 1 < NIT);

        if (pre) {
            int k0 = (it + 1) * BK;
#pragma unroll
            for (int i = 0; i < 2; ++i) {
                int f = i * 512 + tid;
                pa[i]  = *(const float4*)&A[(size_t)(m0 + (f >> 3)) * D_SZ + k0 + (f & 7) * 4];
                pbh[i] = *(const uint4*)&g_bh[(size_t)(k0 + (f >> 5)) * H_SZ + (f & 31) * 4];
                pbl[i] = *(const uint4*)&g_bl[(size_t)(k0 + (f >> 5)) * H_SZ + (f & 31) * 4];
            }
        }

        const uint32_t* AsH = &smem[OFF_AH(cur)];
        const uint32_t* AsL = &smem[OFF_AL(cur)];
        const uint32_t* BsH = &smem[OFF_BH(cur)];
        const uint32_t* BsL = &smem[OFF_BL(cur)];

#pragma unroll
        for (int ks = 0; ks < 4; ++ks) {
            uint32_t aH[2][4], aL[2][4], bH[4][2], bL[4][2];
#pragma unroll
            for (int mi = 0; mi < 2; ++mi) {
                int base = (wm + mi * 16 + g) * AS_STRIDE + ks * 8 + tg;
                aH[mi][0] = AsH[base];
                aH[mi][1] = AsH[base + 8 * AS_STRIDE];
                aH[mi][2] = AsH[base + 4];
                aH[mi][3] = AsH[base + 8 * AS_STRIDE + 4];
                aL[mi][0] = AsL[base];
                aL[mi][1] = AsL[base + 8 * AS_STRIDE];
                aL[mi][2] = AsL[base + 4];
                aL[mi][3] = AsL[base + 8 * AS_STRIDE + 4];
            }
#pragma unroll
            for (int ni = 0; ni < 4; ++ni) {
                int base = (ks * 8 + tg) * BS_STRIDE + wn + ni * 8 + g;
                bH[ni][0] = BsH[base];
                bH[ni][1] = BsH[base + 4 * BS_STRIDE];
                bL[ni][0] = BsL[base];
                bL[ni][1] = BsL[base + 4 * BS_STRIDE];
            }
#pragma unroll
            for (int mi = 0; mi < 2; ++mi)
#pragma unroll
                for (int ni = 0; ni < 4; ++ni) {
                    float* c = acc[mi][ni];
                    MMA_TF32(c, aL[mi][0], aL[mi][1], aL[mi][2], aL[mi][3],
                             bH[ni][0], bH[ni][1]);
                    MMA_TF32(c, aH[mi][0], aH[mi][1], aH[mi][2], aH[mi][3],
                             bL[ni][0], bL[ni][1]);
                    MMA_TF32(c, aH[mi][0], aH[mi][1], aH[mi][2], aH[mi][3],
                             bH[ni][0], bH[ni][1]);
                }
        }

        if (pre) {
            const int nxt = cur ^ 1;
#pragma unroll
            for (int i = 0; i < 2; ++i) {
                int f = i * 512 + tid;
                uint4 h4, l4;
                split_tf32(pa[i].x, h4.x, l4.x); split_tf32(pa[i].y, h4.y, l4.y);
                split_tf32(pa[i].z, h4.z, l4.z); split_tf32(pa[i].w, h4.w, l4.w);
                int ao = (f >> 3) * AS_STRIDE + (f & 7) * 4;
                *(uint4*)&smem[OFF_AH(nxt) + ao] = h4;
                *(uint4*)&smem[OFF_AL(nxt) + ao] = l4;
                int bo = (f >> 5) * BS_STRIDE + (f & 31) * 4;
                *(uint4*)&smem[OFF_BH(nxt) + bo] = pbh[i];
                *(uint4*)&smem[OFF_BL(nxt) + bo] = pbl[i];
            }
        }

        // drain RZ accumulators into RN sums every 2 iters (64 k), validated
        if ((it & 1) == 1) {
#pragma unroll
            for (int mi = 0; mi < 2; ++mi)
#pragma unroll
                for (int ni = 0; ni < 4; ++ni)
#pragma unroll
                    for (int c = 0; c < 4; ++c) {
                        sum[mi][ni][c] += acc[mi][ni][c];
                        acc[mi][ni][c] = 0.0f;
                    }
        }
    }

    // ---- epilogue stage A: rank-1 terms, bias, silu -> hs in smem (stage 0) ----
    float* hs = (float*)smem;                       // [128][HS_STRIDE]
    {
        const float step = stepp[0];
        float colc[4][2], w2r[4][2], w3r[4][2];
#pragma unroll
        for (int ni = 0; ni < 4; ++ni)
#pragma unroll
            for (int j = 0; j < 2; ++j) {
                int col = wn + ni * 8 + 2 * tg + j;
                colc[ni][j] = fmaf(step, W1[(size_t)D_SZ * H_SZ + col], b1[col]);
                w2r[ni][j]  = W1[(size_t)(D_SZ + 1) * H_SZ + col];
                w3r[ni][j]  = W1[(size_t)(D_SZ + 2) * H_SZ + col];
            }
#pragma unroll
        for (int mi = 0; mi < 2; ++mi) {
            int lr0 = wm + mi * 16 + g;
            int lr1 = lr0 + 8;
            float hv0 = hn[m0 + lr0], cv0 = conf[m0 + lr0];
            float hv1 = hn[m0 + lr1], cv1 = conf[m0 + lr1];
#pragma unroll
            for (int ni = 0; ni < 4; ++ni) {
                int col0 = wn + ni * 8 + 2 * tg;
                float x00 = sum[mi][ni][0] + colc[ni][0] + hv0 * w2r[ni][0] + cv0 * w3r[ni][0];
                float x01 = sum[mi][ni][1] + colc[ni][1] + hv0 * w2r[ni][1] + cv0 * w3r[ni][1];
                float x10 = sum[mi][ni][2] + colc[ni][0] + hv1 * w2r[ni][0] + cv1 * w3r[ni][0];
                float x11 = sum[mi][ni][3] + colc[ni][1] + hv1 * w2r[ni][1] + cv1 * w3r[ni][1];
                float2 s0, s1;
                s0.x = x00 / (1.0f + expf(-x00));
                s0.y = x01 / (1.0f + expf(-x01));
                s1.x = x10 / (1.0f + expf(-x10));
                s1.y = x11 / (1.0f + expf(-x11));
                *(float2*)&hs[lr0 * HS_STRIDE + col0] = s0;
                *(float2*)&hs[lr1 * HS_STRIDE + col0] = s1;
            }
        }
    }
    __syncthreads();

    // ---- epilogue stage B: load W2 pair-permuted into stage-1 smem ----
    float2* ws2 = (float2*)&smem[STG];              // [H_SZ][32] pairs (e, e+32)
    for (int i = tid; i < H_SZ * 32; i += 512) {
        int k = i >> 5, j = i & 31;
        ws2[i] = make_float2(W2[k * E_SZ + j], W2[k * E_SZ + j + 32]);
    }
    __syncthreads();

    // ---- epilogue stage C: per-warp GEMV + top-8 + softmax for 8 rows ----
    {
        const float bz0 = b2[lane];
        const float bz1 = b2[lane + 32];
        float acc0[8], acc1[8];
#pragma unroll
        for (int rr = 0; rr < 8; ++rr) { acc0[rr] = bz0; acc1[rr] = bz1; }

        const float* hrow = &hs[(w * 8) * HS_STRIDE];
        for (int k = 0; k < H_SZ; ++k) {
            float2 wv = ws2[k * 32 + lane];
#pragma unroll
            for (int rr = 0; rr < 8; ++rr) {
                float hv = hrow[rr * HS_STRIDE + k];    // LDS broadcast
                acc0[rr] = fmaf(hv, wv.x, acc0[rr]);
                acc1[rr] = fmaf(hv, wv.y, acc1[rr]);
            }
        }

        float* out_w = out;
        float* out_l = out + (size_t)B_SZ * E_SZ;
#pragma unroll
        for (int rr = 0; rr < 8; ++rr) {
            const int r = m0 + w * 8 + rr;
            const float a0 = acc0[rr], a1 = acc1[rr];
            out_l[(size_t)r * E_SZ + lane]      = a0;
            out_l[(size_t)r * E_SZ + lane + 32] = a1;

            bool used0 = false, used1 = false;
            float tv[K_TOP];
            int   ti[K_TOP];
#pragma unroll
            for (int t = 0; t < K_TOP; ++t) {
                float mv = -3.402823466e38f;
                int   mi = 1 << 30;
                if (!used0) { mv = a0; mi = lane; }
                if (!used1 && (a1 > mv || (a1 == mv && lane + 32 < mi))) {
                    mv = a1; mi = lane + 32;
                }
#pragma unroll
                for (int off = 16; off > 0; off >>= 1) {
                    float ov = __shfl_xor_sync(0xffffffffu, mv, off);
                    int   oi = __shfl_xor_sync(0xffffffffu, mi, off);
                    if (ov > mv || (ov == mv && oi < mi)) { mv = ov; mi = oi; }
                }
                tv[t] = mv;
                ti[t] = mi;
                if (mi == lane)      used0 = true;
                if (mi == lane + 32) used1 = true;
            }

            float mx = tv[0];
            float s = 0.0f;
            float ev[K_TOP];
#pragma unroll
            for (int t = 0; t < K_TOP; ++t) { ev[t] = expf(tv[t] - mx); s += ev[t]; }
            float inv = 1.0f / s;

            float w0 = 0.0f, w1 = 0.0f;
#pragma unroll
            for (int t = 0; t < K_TOP; ++t) {
                float e = ev[t] * inv;
                if (ti[t] == lane)      w0 = e;
                if (ti[t] == lane + 32) w1 = e;
            }
            out_w[(size_t)r * E_SZ + lane]      = w0;
            out_w[(size_t)r * E_SZ + lane + 32] = w1;
        }
    }
}

// ---------------------------------------------------------------------------
extern "C" void kernel_launch(void* const* d_in, const int* in_sizes, int n_in,
                              void* d_out, int out_size) {
    const float* r_pooled    = (const float*)d_in[0];
    const float* step_frac   = (const float*)d_in[1];
    const float* hidden_norm = (const float*)d_in[2];
    const float* confidence  = (const float*)d_in[3];
    const float* W1          = (const float*)d_in[4];
    const float* b1          = (const float*)d_in[5];
    const float* W2          = (const float*)d_in[6];
    const float* b2          = (const float*)d_in[7];
    float* out = (float*)d_out;

    cudaFuncSetAttribute(fused_router_kernel,
                         cudaFuncAttributeMaxDynamicSharedMemorySize,
                         SMEM_U32 * 4);

    prep_b_kernel<<<D_SZ * H_SZ / (256 * 4), 256>>>(W1);
    fused_router_kernel<<<B_SZ / 128, 512, SMEM_U32 * 4>>>(
        r_pooled, W1, b1, step_frac, hidden_norm, confidence, W2, b2, out);
}

// round 13
// speedup vs baseline: 1.6357x; 1.6357x over previous
#include <cuda_runtime.h>
#include <math.h>
#include <stdint.h>

#define B_SZ 16384
#define D_SZ 4096
#define H_SZ 128
#define E_SZ 64
#define K_TOP 8

// Pre-split W1 (tf32 hi/lo bit patterns), [k][n] layout, 2 MB each.
__device__ uint32_t g_bh[D_SZ * H_SZ];
__device__ uint32_t g_bl[D_SZ * H_SZ];

__device__ __forceinline__ uint32_t f2tf32(float x) {
    uint32_t r;
    asm("cvt.rna.tf32.f32 %0, %1;" : "=r"(r) : "f"(x));
    return r;
}
__device__ __forceinline__ void split_tf32(float x, uint32_t& hi, uint32_t& lo) {
    hi = f2tf32(x);
    lo = f2tf32(x - __uint_as_float(hi));
}
__device__ __forceinline__ uint32_t smem_u32(const void* p) {
    uint32_t a;
    asm("{ .reg .u64 t; cvta.to.shared.u64 t, %1; cvt.u32.u64 %0, t; }"
        : "=r"(a) : "l"(p));
    return a;
}

#define CP_ASYNC16(dst_u32, src_ptr)                                          \
    asm volatile("cp.async.cg.shared.global [%0], [%1], 16;"                  \
                 :: "r"(dst_u32), "l"(src_ptr))
#define CP_ASYNC_COMMIT() asm volatile("cp.async.commit_group;" ::: "memory")
#define CP_ASYNC_WAIT0()  asm volatile("cp.async.wait_group 0;" ::: "memory")

#define MMA_TF32(C, A0, A1, A2, A3, B0, B1)                                   \
    asm volatile(                                                             \
        "mma.sync.aligned.m16n8k8.row.col.f32.tf32.tf32.f32 "                 \
        "{%0,%1,%2,%3}, {%4,%5,%6,%7}, {%8,%9}, {%0,%1,%2,%3};"               \
        : "+f"(C[0]), "+f"(C[1]), "+f"(C[2]), "+f"(C[3])                      \
        : "r"(A0), "r"(A1), "r"(A2), "r"(A3), "r"(B0), "r"(B1))

// ---------------------------------------------------------------------------
// Prep: split W1[0:4096][0:128] into tf32 hi/lo, same [k][n] layout.
// ---------------------------------------------------------------------------
__global__ __launch_bounds__(256)
void prep_b_kernel(const float* __restrict__ W1) {
    int idx = (blockIdx.x * 256 + threadIdx.x) * 4;
    float4 v = *(const float4*)&W1[idx];
    uint4 h4, l4;
    split_tf32(v.x, h4.x, l4.x); split_tf32(v.y, h4.y, l4.y);
    split_tf32(v.z, h4.z, l4.z); split_tf32(v.w, h4.w, l4.w);
    *(uint4*)&g_bh[idx] = h4;
    *(uint4*)&g_bl[idx] = l4;
}

// ---------------------------------------------------------------------------
// Fused kernel: h = silu(features @ W1 + b1) [3xTF32 mma.sync, 2-stage pipe]
// then logits = h @ W2 + b2, top-8, softmax, scatter [in-block epilogue].
// BM=128, BN=128(H), BK=32. 512 threads = 16 warps (4m x 4n), warp tile 32x32.
// B tiles stream pre-split via cp.async (zero register staging).
// ---------------------------------------------------------------------------
#define BK 32
#define AS_STRIDE 36   // bank(4r + 8ks + tg): frag loads conflict-free
#define BS_STRIDE 136  // bank(8tg + g): frag loads conflict-free

#define A_STG   (128 * AS_STRIDE)        // 4608 u32
#define B_STG   (BK * BS_STRIDE)         // 4352 u32
#define STG     (2 * A_STG + 2 * B_STG)  // 17920 u32 per stage
#define OFF_AH(s) ((s) * STG + 0)
#define OFF_AL(s) ((s) * STG + A_STG)
#define OFF_BH(s) ((s) * STG + 2 * A_STG)
#define OFF_BL(s) ((s) * STG + 2 * A_STG + B_STG)
#define SMEM_U32  (2 * STG)              // 35840 u32 = 143360 bytes

// epilogue overlays: hs (128 x HS_STRIDE f32) on stage 0, ws2 pairs on stage 1
#define HS_STRIDE 132                    // 128*132 = 16896 u32 <= STG

__global__ __launch_bounds__(512)
void fused_router_kernel(const float* __restrict__ A,     // (B, D)
                         const float* __restrict__ W1,    // (D+3, H)
                         const float* __restrict__ b1,    // (H)
                         const float* __restrict__ stepp, // (1)
                         const float* __restrict__ hn,    // (B)
                         const float* __restrict__ conf,  // (B)
                         const float* __restrict__ W2,    // (H, E)
                         const float* __restrict__ b2,    // (E)
                         float* __restrict__ out)
{
    extern __shared__ uint32_t smem[];
    const uint32_t sb = smem_u32(smem);

    const int tid  = threadIdx.x;
    const int lane = tid & 31;
    const int w    = tid >> 5;
    const int wm   = (w & 3) * 32;   // 4 warps in m
    const int wn   = (w >> 2) * 32;  // 4 warps in n
    const int g    = lane >> 2;
    const int tg   = lane & 3;
    const int m0   = blockIdx.x * 128;

    // B copy mapping (per stage, 2 x 16B hi + 2 x 16B lo per thread):
    // f = i*512+tid; brow = f>>5 (0..31); bc = (f&31)*4
    const int brow0 = tid >> 5;                 // i=0
    const int bc0   = (tid & 31) * 4;
    const int brow1 = (512 + tid) >> 5;         // i=1
    const int bc1   = bc0;                      // (512+tid)&31 == tid&31
    const uint32_t bdst0 = brow0 * BS_STRIDE + bc0;
    const uint32_t bdst1 = brow1 * BS_STRIDE + bc1;

    float acc[2][4][4];
    float sum[2][4][4];
#pragma unroll
    for (int mi = 0; mi < 2; ++mi)
#pragma unroll
        for (int ni = 0; ni < 4; ++ni)
#pragma unroll
            for (int c = 0; c < 4; ++c) { acc[mi][ni][c] = 0.0f; sum[mi][ni][c] = 0.0f; }

    // A writer mapping: f=i*512+tid, arow=f>>3, ak=(f&7)*4
    float4 pa[2];
#pragma unroll
    for (int i = 0; i < 2; ++i) {
        int f = i * 512 + tid;
        pa[i] = *(const float4*)&A[(size_t)(m0 + (f >> 3)) * D_SZ + (f & 7) * 4];
    }

    // prologue: stage 0 — B via cp.async, A via split+STS
    CP_ASYNC16(sb + (OFF_BH(0) + bdst0) * 4, &g_bh[(size_t)brow0 * H_SZ + bc0]);
    CP_ASYNC16(sb + (OFF_BH(0) + bdst1) * 4, &g_bh[(size_t)brow1 * H_SZ + bc1]);
    CP_ASYNC16(sb + (OFF_BL(0) + bdst0) * 4, &g_bl[(size_t)brow0 * H_SZ + bc0]);
    CP_ASYNC16(sb + (OFF_BL(0) + bdst1) * 4, &g_bl[(size_t)brow1 * H_SZ + bc1]);
    CP_ASYNC_COMMIT();
#pragma unroll
    for (int i = 0; i < 2; ++i) {
        int f = i * 512 + tid;
        uint4 h4, l4;
        split_tf32(pa[i].x, h4.x, l4.x); split_tf32(pa[i].y, h4.y, l4.y);
        split_tf32(pa[i].z, h4.z, l4.z); split_tf32(pa[i].w, h4.w, l4.w);
        int ao = (f >> 3) * AS_STRIDE + (f & 7) * 4;
        *(uint4*)&smem[OFF_AH(0) + ao] = h4;
        *(uint4*)&smem[OFF_AL(0) + ao] = l4;
    }
    CP_ASYNC_WAIT0();

    const int NIT = D_SZ / BK;   // 128
    for (int it = 0; it < NIT; ++it) {
        __syncthreads();   // stage 'cur' fully written & visible; prior reads done
        const int cur = it & 1;
        const bool pre = (it + 1 < NIT);

        if (pre) {
            const int nxt = cur ^ 1;
            const int k0 = (it + 1) * BK;
            // B for stage nxt: async, no registers
            CP_ASYNC16(sb + (OFF_BH(nxt) + bdst0) * 4, &g_bh[(size_t)(k0 + brow0) * H_SZ + bc0]);
            CP_ASYNC16(sb + (OFF_BH(nxt) + bdst1) * 4, &g_bh[(size_t)(k0 + brow1) * H_SZ + bc1]);
            CP_ASYNC16(sb + (OFF_BL(nxt) + bdst0) * 4, &g_bl[(size_t)(k0 + brow0) * H_SZ + bc0]);
            CP_ASYNC16(sb + (OFF_BL(nxt) + bdst1) * 4, &g_bl[(size_t)(k0 + brow1) * H_SZ + bc1]);
            CP_ASYNC_COMMIT();
            // A prefetch into registers
#pragma unroll
            for (int i = 0; i < 2; ++i) {
                int f = i * 512 + tid;
                pa[i] = *(const float4*)&A[(size_t)(m0 + (f >> 3)) * D_SZ + k0 + (f & 7) * 4];
            }
        }

        const uint32_t* AsH = &smem[OFF_AH(cur)];
        const uint32_t* AsL = &smem[OFF_AL(cur)];
        const uint32_t* BsH = &smem[OFF_BH(cur)];
        const uint32_t* BsL = &smem[OFF_BL(cur)];

#pragma unroll
        for (int ks = 0; ks < 4; ++ks) {
            uint32_t aH[2][4], aL[2][4], bH[4][2], bL[4][2];
#pragma unroll
            for (int mi = 0; mi < 2; ++mi) {
                int base = (wm + mi * 16 + g) * AS_STRIDE + ks * 8 + tg;
                aH[mi][0] = AsH[base];
                aH[mi][1] = AsH[base + 8 * AS_STRIDE];
                aH[mi][2] = AsH[base + 4];
                aH[mi][3] = AsH[base + 8 * AS_STRIDE + 4];
                aL[mi][0] = AsL[base];
                aL[mi][1] = AsL[base + 8 * AS_STRIDE];
                aL[mi][2] = AsL[base + 4];
                aL[mi][3] = AsL[base + 8 * AS_STRIDE + 4];
            }
#pragma unroll
            for (int ni = 0; ni < 4; ++ni) {
                int base = (ks * 8 + tg) * BS_STRIDE + wn + ni * 8 + g;
                bH[ni][0] = BsH[base];
                bH[ni][1] = BsH[base + 4 * BS_STRIDE];
                bL[ni][0] = BsL[base];
                bL[ni][1] = BsL[base + 4 * BS_STRIDE];
            }
#pragma unroll
            for (int mi = 0; mi < 2; ++mi)
#pragma unroll
                for (int ni = 0; ni < 4; ++ni) {
                    float* c = acc[mi][ni];
                    MMA_TF32(c, aL[mi][0], aL[mi][1], aL[mi][2], aL[mi][3],
                             bH[ni][0], bH[ni][1]);
                    MMA_TF32(c, aH[mi][0], aH[mi][1], aH[mi][2], aH[mi][3],
                             bL[ni][0], bL[ni][1]);
                    MMA_TF32(c, aH[mi][0], aH[mi][1], aH[mi][2], aH[mi][3],
                             bH[ni][0], bH[ni][1]);
                }
        }

        if (pre) {   // split + store A into stage nxt
            const int nxt = cur ^ 1;
#pragma unroll
            for (int i = 0; i < 2; ++i) {
                int f = i * 512 + tid;
                uint4 h4, l4;
                split_tf32(pa[i].x, h4.x, l4.x); split_tf32(pa[i].y, h4.y, l4.y);
                split_tf32(pa[i].z, h4.z, l4.z); split_tf32(pa[i].w, h4.w, l4.w);
                int ao = (f >> 3) * AS_STRIDE + (f & 7) * 4;
                *(uint4*)&smem[OFF_AH(nxt) + ao] = h4;
                *(uint4*)&smem[OFF_AL(nxt) + ao] = l4;
            }
        }

        // drain RZ accumulators into RN sums every 2 iters (64 k), validated
        if ((it & 1) == 1) {
#pragma unroll
            for (int mi = 0; mi < 2; ++mi)
#pragma unroll
                for (int ni = 0; ni < 4; ++ni)
#pragma unroll
                    for (int c = 0; c < 4; ++c) {
                        sum[mi][ni][c] += acc[mi][ni][c];
                        acc[mi][ni][c] = 0.0f;
                    }
        }

        if (pre) CP_ASYNC_WAIT0();   // own async copies done before next barrier
    }

    // ---- epilogue stage A: rank-1 terms, bias, silu -> hs in smem (stage 0) ----
    float* hs = (float*)smem;                       // [128][HS_STRIDE]
    {
        const float step = stepp[0];
        float colc[4][2], w2r[4][2], w3r[4][2];
#pragma unroll
        for (int ni = 0; ni < 4; ++ni)
#pragma unroll
            for (int j = 0; j < 2; ++j) {
                int col = wn + ni * 8 + 2 * tg + j;
                colc[ni][j] = fmaf(step, W1[(size_t)D_SZ * H_SZ + col], b1[col]);
                w2r[ni][j]  = W1[(size_t)(D_SZ + 1) * H_SZ + col];
                w3r[ni][j]  = W1[(size_t)(D_SZ + 2) * H_SZ + col];
            }
#pragma unroll
        for (int mi = 0; mi < 2; ++mi) {
            int lr0 = wm + mi * 16 + g;
            int lr1 = lr0 + 8;
            float hv0 = hn[m0 + lr0], cv0 = conf[m0 + lr0];
            float hv1 = hn[m0 + lr1], cv1 = conf[m0 + lr1];
#pragma unroll
            for (int ni = 0; ni < 4; ++ni) {
                int col0 = wn + ni * 8 + 2 * tg;
                float x00 = sum[mi][ni][0] + colc[ni][0] + hv0 * w2r[ni][0] + cv0 * w3r[ni][0];
                float x01 = sum[mi][ni][1] + colc[ni][1] + hv0 * w2r[ni][1] + cv0 * w3r[ni][1];
                float x10 = sum[mi][ni][2] + colc[ni][0] + hv1 * w2r[ni][0] + cv1 * w3r[ni][0];
                float x11 = sum[mi][ni][3] + colc[ni][1] + hv1 * w2r[ni][1] + cv1 * w3r[ni][1];
                float2 s0, s1;
                s0.x = x00 / (1.0f + expf(-x00));
                s0.y = x01 / (1.0f + expf(-x01));
                s1.x = x10 / (1.0f + expf(-x10));
                s1.y = x11 / (1.0f + expf(-x11));
                *(float2*)&hs[lr0 * HS_STRIDE + col0] = s0;
                *(float2*)&hs[lr1 * HS_STRIDE + col0] = s1;
            }
        }
    }
    __syncthreads();

    // ---- epilogue stage B: load W2 pair-permuted into stage-1 smem ----
    float2* ws2 = (float2*)&smem[STG];              // [H_SZ][32] pairs (e, e+32)
    for (int i = tid; i < H_SZ * 32; i += 512) {
        int k = i >> 5, j = i & 31;
        ws2[i] = make_float2(W2[k * E_SZ + j], W2[k * E_SZ + j + 32]);
    }
    __syncthreads();

    // ---- epilogue stage C: per-warp GEMV + top-8 + softmax for 8 rows ----
    {
        const float bz0 = b2[lane];
        const float bz1 = b2[lane + 32];
        float acc0[8], acc1[8];
#pragma unroll
        for (int rr = 0; rr < 8; ++rr) { acc0[rr] = bz0; acc1[rr] = bz1; }

        const float* hrow = &hs[(w * 8) * HS_STRIDE];
        for (int k = 0; k < H_SZ; ++k) {
            float2 wv = ws2[k * 32 + lane];
#pragma unroll
            for (int rr = 0; rr < 8; ++rr) {
                float hv = hrow[rr * HS_STRIDE + k];    // LDS broadcast
                acc0[rr] = fmaf(hv, wv.x, acc0[rr]);
                acc1[rr] = fmaf(hv, wv.y, acc1[rr]);
            }
        }

        float* out_w = out;
        float* out_l = out + (size_t)B_SZ * E_SZ;
#pragma unroll
        for (int rr = 0; rr < 8; ++rr) {
            const int r = m0 + w * 8 + rr;
            const float a0 = acc0[rr], a1 = acc1[rr];
            out_l[(size_t)r * E_SZ + lane]      = a0;
            out_l[(size_t)r * E_SZ + lane + 32] = a1;

            bool used0 = false, used1 = false;
            float tv[K_TOP];
            int   ti[K_TOP];
#pragma unroll
            for (int t = 0; t < K_TOP; ++t) {
                float mv = -3.402823466e38f;
                int   mi = 1 << 30;
                if (!used0) { mv = a0; mi = lane; }
                if (!used1 && (a1 > mv || (a1 == mv && lane + 32 < mi))) {
                    mv = a1; mi = lane + 32;
                }
#pragma unroll
                for (int off = 16; off > 0; off >>= 1) {
                    float ov = __shfl_xor_sync(0xffffffffu, mv, off);
                    int   oi = __shfl_xor_sync(0xffffffffu, mi, off);
                    if (ov > mv || (ov == mv && oi < mi)) { mv = ov; mi = oi; }
                }
                tv[t] = mv;
                ti[t] = mi;
                if (mi == lane)      used0 = true;
                if (mi == lane + 32) used1 = true;
            }

            float mx = tv[0];
            float s = 0.0f;
            float ev[K_TOP];
#pragma unroll
            for (int t = 0; t < K_TOP; ++t) { ev[t] = expf(tv[t] - mx); s += ev[t]; }
            float inv = 1.0f / s;

            float w0 = 0.0f, w1 = 0.0f;
#pragma unroll
            for (int t = 0; t < K_TOP; ++t) {
                float e = ev[t] * inv;
                if (ti[t] == lane)      w0 = e;
                if (ti[t] == lane + 32) w1 = e;
            }
            out_w[(size_t)r * E_SZ + lane]      = w0;
            out_w[(size_t)r * E_SZ + lane + 32] = w1;
        }
    }
}

// ---------------------------------------------------------------------------
extern "C" void kernel_launch(void* const* d_in, const int* in_sizes, int n_in,
                              void* d_out, int out_size) {
    const float* r_pooled    = (const float*)d_in[0];
    const float* step_frac   = (const float*)d_in[1];
    const float* hidden_norm = (const float*)d_in[2];
    const float* confidence  = (const float*)d_in[3];
    const float* W1          = (const float*)d_in[4];
    const float* b1          = (const float*)d_in[5];
    const float* W2          = (const float*)d_in[6];
    const float* b2          = (const float*)d_in[7];
    float* out = (float*)d_out;

    cudaFuncSetAttribute(fused_router_kernel,
                         cudaFuncAttributeMaxDynamicSharedMemorySize,
                         SMEM_U32 * 4);

    prep_b_kernel<<<D_SZ * H_SZ / (256 * 4), 256>>>(W1);
    fused_router_kernel<<<B_SZ / 128, 512, SMEM_U32 * 4>>>(
        r_pooled, W1, b1, step_frac, hidden_norm, confidence, W2, b2, out);
}

// round 14
// speedup vs baseline: 1.9579x; 1.1970x over previous
#include <cuda_runtime.h>
#include <cuda_fp16.h>
#include <math.h>
#include <stdint.h>

#define B_SZ 16384
#define D_SZ 4096
#define H_SZ 128
#define E_SZ 64
#define K_TOP 8

// Pre-split W1: tf32 hi bits + packed fp16 cross pairs, [k][n] layout, 2 MB each.
__device__ uint32_t g_bh[D_SZ * H_SZ];   // tf32(b) bit patterns
__device__ uint32_t g_bc[D_SZ * H_SZ];   // half2(bL*64, bH/64)

__device__ __forceinline__ uint32_t f2tf32(float x) {
    uint32_t r;
    asm("cvt.rna.tf32.f32 %0, %1;" : "=r"(r) : "f"(x));
    return r;
}
__device__ __forceinline__ uint32_t smem_u32(const void* p) {
    uint32_t a;
    asm("{ .reg .u64 t; cvta.to.shared.u64 t, %1; cvt.u32.u64 %0, t; }"
        : "=r"(a) : "l"(p));
    return a;
}
__device__ __forceinline__ uint32_t pack_h2(float lo_slot, float hi_slot) {
    // .x (virtual-even) = lo_slot, .y (virtual-odd) = hi_slot
    __half2 h = __floats2half2_rn(lo_slot, hi_slot);
    return *(uint32_t*)&h;
}

#define CP_ASYNC16(dst_u32, src_ptr)                                          \
    asm volatile("cp.async.cg.shared.global [%0], [%1], 16;"                  \
                 :: "r"(dst_u32), "l"(src_ptr))
#define CP_ASYNC_COMMIT() asm volatile("cp.async.commit_group;" ::: "memory")
#define CP_ASYNC_WAIT0()  asm volatile("cp.async.wait_group 0;" ::: "memory")

#define MMA_TF32(C, A0, A1, A2, A3, B0, B1)                                   \
    asm volatile(                                                             \
        "mma.sync.aligned.m16n8k8.row.col.f32.tf32.tf32.f32 "                 \
        "{%0,%1,%2,%3}, {%4,%5,%6,%7}, {%8,%9}, {%0,%1,%2,%3};"               \
        : "+f"(C[0]), "+f"(C[1]), "+f"(C[2]), "+f"(C[3])                      \
        : "r"(A0), "r"(A1), "r"(A2), "r"(A3), "r"(B0), "r"(B1))

#define MMA_F16(C, A0, A1, A2, A3, B0, B1)                                    \
    asm volatile(                                                             \
        "mma.sync.aligned.m16n8k16.row.col.f32.f16.f16.f32 "                  \
        "{%0,%1,%2,%3}, {%4,%5,%6,%7}, {%8,%9}, {%0,%1,%2,%3};"               \
        : "+f"(C[0]), "+f"(C[1]), "+f"(C[2]), "+f"(C[3])                      \
        : "r"(A0), "r"(A1), "r"(A2), "r"(A3), "r"(B0), "r"(B1))

// ---------------------------------------------------------------------------
// Prep: W1 -> tf32 hi bits (g_bh) + packed fp16 cross pairs (g_bc).
// Cross pair for element b: half2(bL*64, bH/64) where bH=tf32(b), bL=b-bH.
// ---------------------------------------------------------------------------
__global__ __launch_bounds__(256)
void prep_b_kernel(const float* __restrict__ W1) {
    int idx = (blockIdx.x * 256 + threadIdx.x) * 4;
    float4 v = *(const float4*)&W1[idx];
    uint4 h4, c4;
    const float* pv = &v.x;
    uint32_t* ph = &h4.x;
    uint32_t* pc = &c4.x;
#pragma unroll
    for (int j = 0; j < 4; ++j) {
        uint32_t hb = f2tf32(pv[j]);
        float hf = __uint_as_float(hb);
        float lf = pv[j] - hf;
        ph[j] = hb;
        pc[j] = pack_h2(lf * 64.0f, hf * 0.015625f);   // (bL*64, bH/64)
    }
    *(uint4*)&g_bh[idx] = h4;
    *(uint4*)&g_bc[idx] = c4;
}

// ---------------------------------------------------------------------------
// Fused kernel: h = silu(features @ W1 + b1), then router epilogue.
// BM=128, BN=128(H), BK=32. 512 threads = 16 warps (4m x 4n), warp tile 32x32.
// Per k8 step: 1 tf32 MMA (aH*bH) + 1 fp16 k16 MMA (packed aH*bL + aL*bH):
// 64 MMA/warp-iter vs 96 for classic 3xTF32.
// ---------------------------------------------------------------------------
#define BK 32
#define AS_STRIDE 36   // bank(4g+tg) conflict-free for frag loads
#define BS_STRIDE 136  // bank(8tg+g) conflict-free

#define A_STG   (128 * AS_STRIDE)        // 4608 u32 (AsH)
#define AC_STG  (128 * AS_STRIDE)        // 4608 u32 (Ac fp16 pairs)
#define B_STG   (BK * BS_STRIDE)         // 4352 u32 (BsH)
#define BC_STG  (BK * BS_STRIDE)         // 4352 u32 (Bc fp16 pairs)
#define STG     (A_STG + AC_STG + B_STG + BC_STG)   // 17920 u32 per stage
#define OFF_AH(s) ((s) * STG + 0)
#define OFF_AC(s) ((s) * STG + A_STG)
#define OFF_BH(s) ((s) * STG + A_STG + AC_STG)
#define OFF_BC(s) ((s) * STG + A_STG + AC_STG + B_STG)
#define SMEM_U32  (2 * STG)              // 35840 u32 = 143360 bytes

#define HS_STRIDE 132                    // epilogue hs overlay on stage 0

__global__ __launch_bounds__(512)
void fused_router_kernel(const float* __restrict__ A,     // (B, D)
                         const float* __restrict__ W1,    // (D+3, H)
                         const float* __restrict__ b1,    // (H)
                         const float* __restrict__ stepp, // (1)
                         const float* __restrict__ hn,    // (B)
                         const float* __restrict__ conf,  // (B)
                         const float* __restrict__ W2,    // (H, E)
                         const float* __restrict__ b2,    // (E)
                         float* __restrict__ out)
{
    extern __shared__ uint32_t smem[];
    const uint32_t sb = smem_u32(smem);

    const int tid  = threadIdx.x;
    const int lane = tid & 31;
    const int w    = tid >> 5;
    const int wm   = (w & 3) * 32;   // 4 warps in m
    const int wn   = (w >> 2) * 32;  // 4 warps in n
    const int g    = lane >> 2;
    const int tg   = lane & 3;
    const int m0   = blockIdx.x * 128;

    // B copy mapping (per stage, per tile: 2 x 16B): f=i*512+tid,
    // brow=f>>5, bc=(f&31)*4
    const int brow0 = tid >> 5;
    const int bc0   = (tid & 31) * 4;
    const int brow1 = (512 + tid) >> 5;
    const uint32_t bdst0 = brow0 * BS_STRIDE + bc0;
    const uint32_t bdst1 = brow1 * BS_STRIDE + bc0;

    float acc[2][4][4];
    float sum[2][4][4];
#pragma unroll
    for (int mi = 0; mi < 2; ++mi)
#pragma unroll
        for (int ni = 0; ni < 4; ++ni)
#pragma unroll
            for (int c = 0; c < 4; ++c) { acc[mi][ni][c] = 0.0f; sum[mi][ni][c] = 0.0f; }

    // A writer mapping: f=i*512+tid, arow=f>>3, ak=(f&7)*4
    float4 pa[2];
#pragma unroll
    for (int i = 0; i < 2; ++i) {
        int f = i * 512 + tid;
        pa[i] = *(const float4*)&A[(size_t)(m0 + (f >> 3)) * D_SZ + (f & 7) * 4];
    }

    // prologue: stage 0
    CP_ASYNC16(sb + (OFF_BH(0) + bdst0) * 4, &g_bh[(size_t)brow0 * H_SZ + bc0]);
    CP_ASYNC16(sb + (OFF_BH(0) + bdst1) * 4, &g_bh[(size_t)brow1 * H_SZ + bc0]);
    CP_ASYNC16(sb + (OFF_BC(0) + bdst0) * 4, &g_bc[(size_t)brow0 * H_SZ + bc0]);
    CP_ASYNC16(sb + (OFF_BC(0) + bdst1) * 4, &g_bc[(size_t)brow1 * H_SZ + bc0]);
    CP_ASYNC_COMMIT();
#pragma unroll
    for (int i = 0; i < 2; ++i) {
        int f = i * 512 + tid;
        uint4 h4, c4;
        const float* pv = &pa[i].x;
        uint32_t* ph = &h4.x;
        uint32_t* pc = &c4.x;
#pragma unroll
        for (int j = 0; j < 4; ++j) {
            uint32_t hb = f2tf32(pv[j]);
            float hf = __uint_as_float(hb);
            float lf = pv[j] - hf;
            ph[j] = hb;
            pc[j] = pack_h2(hf * 0.015625f, lf * 64.0f);   // (aH/64, aL*64)
        }
        int ao = (f >> 3) * AS_STRIDE + (f & 7) * 4;
        *(uint4*)&smem[OFF_AH(0) + ao] = h4;
        *(uint4*)&smem[OFF_AC(0) + ao] = c4;
    }
    CP_ASYNC_WAIT0();

    const int NIT = D_SZ / BK;   // 128
    for (int it = 0; it < NIT; ++it) {
        __syncthreads();
        const int cur = it & 1;
        const bool pre = (it + 1 < NIT);

        if (pre) {
            const int nxt = cur ^ 1;
            const int k0 = (it + 1) * BK;
            CP_ASYNC16(sb + (OFF_BH(nxt) + bdst0) * 4, &g_bh[(size_t)(k0 + brow0) * H_SZ + bc0]);
            CP_ASYNC16(sb + (OFF_BH(nxt) + bdst1) * 4, &g_bh[(size_t)(k0 + brow1) * H_SZ + bc0]);
            CP_ASYNC16(sb + (OFF_BC(nxt) + bdst0) * 4, &g_bc[(size_t)(k0 + brow0) * H_SZ + bc0]);
            CP_ASYNC16(sb + (OFF_BC(nxt) + bdst1) * 4, &g_bc[(size_t)(k0 + brow1) * H_SZ + bc0]);
            CP_ASYNC_COMMIT();
#pragma unroll
            for (int i = 0; i < 2; ++i) {
                int f = i * 512 + tid;
                pa[i] = *(const float4*)&A[(size_t)(m0 + (f >> 3)) * D_SZ + k0 + (f & 7) * 4];
            }
        }

        const uint32_t* AsH = &smem[OFF_AH(cur)];
        const uint32_t* Ac  = &smem[OFF_AC(cur)];
        const uint32_t* BsH = &smem[OFF_BH(cur)];
        const uint32_t* Bc  = &smem[OFF_BC(cur)];

#pragma unroll
        for (int ks = 0; ks < 4; ++ks) {
            uint32_t aH[2][4], ca[2][4], bH[4][2], cb[4][2];
#pragma unroll
            for (int mi = 0; mi < 2; ++mi) {
                int base = (wm + mi * 16 + g) * AS_STRIDE + ks * 8 + tg;
                aH[mi][0] = AsH[base];
                aH[mi][1] = AsH[base + 8 * AS_STRIDE];
                aH[mi][2] = AsH[base + 4];
                aH[mi][3] = AsH[base + 8 * AS_STRIDE + 4];
                ca[mi][0] = Ac[base];                     // a0: row g,   vk 2tg
                ca[mi][1] = Ac[base + 8 * AS_STRIDE];     // a1: row g+8, vk 2tg
                ca[mi][2] = Ac[base + 4];                 // a2: row g,   vk 2tg+8
                ca[mi][3] = Ac[base + 8 * AS_STRIDE + 4]; // a3: row g+8, vk 2tg+8
            }
#pragma unroll
            for (int ni = 0; ni < 4; ++ni) {
                int base = (ks * 8 + tg) * BS_STRIDE + wn + ni * 8 + g;
                bH[ni][0] = BsH[base];
                bH[ni][1] = BsH[base + 4 * BS_STRIDE];
                cb[ni][0] = Bc[base];                     // b0: vk 2tg,   col g
                cb[ni][1] = Bc[base + 4 * BS_STRIDE];     // b1: vk 2tg+8, col g
            }
#pragma unroll
            for (int mi = 0; mi < 2; ++mi)
#pragma unroll
                for (int ni = 0; ni < 4; ++ni) {
                    float* c = acc[mi][ni];
                    // packed cross terms: aH*bL + aL*bH (fp16 k16)
                    MMA_F16(c, ca[mi][0], ca[mi][1], ca[mi][2], ca[mi][3],
                            cb[ni][0], cb[ni][1]);
                    // dominant term: aH*bH (tf32 k8)
                    MMA_TF32(c, aH[mi][0], aH[mi][1], aH[mi][2], aH[mi][3],
                             bH[ni][0], bH[ni][1]);
                }
        }

        if (pre) {   // split + pack + store A into stage nxt
            const int nxt = cur ^ 1;
#pragma unroll
            for (int i = 0; i < 2; ++i) {
                int f = i * 512 + tid;
                uint4 h4, c4;
                const float* pv = &pa[i].x;
                uint32_t* ph = &h4.x;
                uint32_t* pc = &c4.x;
#pragma unroll
                for (int j = 0; j < 4; ++j) {
                    uint32_t hb = f2tf32(pv[j]);
                    float hf = __uint_as_float(hb);
                    float lf = pv[j] - hf;
                    ph[j] = hb;
                    pc[j] = pack_h2(hf * 0.015625f, lf * 64.0f);
                }
                int ao = (f >> 3) * AS_STRIDE + (f & 7) * 4;
                *(uint4*)&smem[OFF_AH(nxt) + ao] = h4;
                *(uint4*)&smem[OFF_AC(nxt) + ao] = c4;
            }
        }

        // drain RZ accumulators into RN sums every 2 iters (64 k), validated
        if ((it & 1) == 1) {
#pragma unroll
            for (int mi = 0; mi < 2; ++mi)
#pragma unroll
                for (int ni = 0; ni < 4; ++ni)
#pragma unroll
                    for (int c = 0; c < 4; ++c) {
                        sum[mi][ni][c] += acc[mi][ni][c];
                        acc[mi][ni][c] = 0.0f;
                    }
        }

        if (pre) CP_ASYNC_WAIT0();
    }

    // ---- epilogue stage A: rank-1 terms, bias, silu -> hs in smem (stage 0) ----
    float* hs = (float*)smem;                       // [128][HS_STRIDE]
    {
        const float step = stepp[0];
        float colc[4][2], w2r[4][2], w3r[4][2];
#pragma unroll
        for (int ni = 0; ni < 4; ++ni)
#pragma unroll
            for (int j = 0; j < 2; ++j) {
                int col = wn + ni * 8 + 2 * tg + j;
                colc[ni][j] = fmaf(step, W1[(size_t)D_SZ * H_SZ + col], b1[col]);
                w2r[ni][j]  = W1[(size_t)(D_SZ + 1) * H_SZ + col];
                w3r[ni][j]  = W1[(size_t)(D_SZ + 2) * H_SZ + col];
            }
#pragma unroll
        for (int mi = 0; mi < 2; ++mi) {
            int lr0 = wm + mi * 16 + g;
            int lr1 = lr0 + 8;
            float hv0 = hn[m0 + lr0], cv0 = conf[m0 + lr0];
            float hv1 = hn[m0 + lr1], cv1 = conf[m0 + lr1];
#pragma unroll
            for (int ni = 0; ni < 4; ++ni) {
                int col0 = wn + ni * 8 + 2 * tg;
                float x00 = sum[mi][ni][0] + colc[ni][0] + hv0 * w2r[ni][0] + cv0 * w3r[ni][0];
                float x01 = sum[mi][ni][1] + colc[ni][1] + hv0 * w2r[ni][1] + cv0 * w3r[ni][1];
                float x10 = sum[mi][ni][2] + colc[ni][0] + hv1 * w2r[ni][0] + cv1 * w3r[ni][0];
                float x11 = sum[mi][ni][3] + colc[ni][1] + hv1 * w2r[ni][1] + cv1 * w3r[ni][1];
                float2 s0, s1;
                s0.x = x00 / (1.0f + expf(-x00));
                s0.y = x01 / (1.0f + expf(-x01));
                s1.x = x10 / (1.0f + expf(-x10));
                s1.y = x11 / (1.0f + expf(-x11));
                *(float2*)&hs[lr0 * HS_STRIDE + col0] = s0;
                *(float2*)&hs[lr1 * HS_STRIDE + col0] = s1;
            }
        }
    }
    __syncthreads();

    // ---- epilogue stage B: load W2 pair-permuted into stage-1 smem ----
    float2* ws2 = (float2*)&smem[STG];              // [H_SZ][32] pairs (e, e+32)
    for (int i = tid; i < H_SZ * 32; i += 512) {
        int k = i >> 5, j = i & 31;
        ws2[i] = make_float2(W2[k * E_SZ + j], W2[k * E_SZ + j + 32]);
    }
    __syncthreads();

    // ---- epilogue stage C: per-warp GEMV + top-8 + softmax for 8 rows ----
    {
        const float bz0 = b2[lane];
        const float bz1 = b2[lane + 32];
        float acc0[8], acc1[8];
#pragma unroll
        for (int rr = 0; rr < 8; ++rr) { acc0[rr] = bz0; acc1[rr] = bz1; }

        const float* hrow = &hs[(w * 8) * HS_STRIDE];
        for (int k = 0; k < H_SZ; ++k) {
            float2 wv = ws2[k * 32 + lane];
#pragma unroll
            for (int rr = 0; rr < 8; ++rr) {
                float hv = hrow[rr * HS_STRIDE + k];
                acc0[rr] = fmaf(hv, wv.x, acc0[rr]);
                acc1[rr] = fmaf(hv, wv.y, acc1[rr]);
            }
        }

        float* out_w = out;
        float* out_l = out + (size_t)B_SZ * E_SZ;
#pragma unroll
        for (int rr = 0; rr < 8; ++rr) {
            const int r = m0 + w * 8 + rr;
            const float a0 = acc0[rr], a1 = acc1[rr];
            out_l[(size_t)r * E_SZ + lane]      = a0;
            out_l[(size_t)r * E_SZ + lane + 32] = a1;

            bool used0 = false, used1 = false;
            float tv[K_TOP];
            int   ti[K_TOP];
#pragma unroll
            for (int t = 0; t < K_TOP; ++t) {
                float mv = -3.402823466e38f;
                int   mi = 1 << 30;
                if (!used0) { mv = a0; mi = lane; }
                if (!used1 && (a1 > mv || (a1 == mv && lane + 32 < mi))) {
                    mv = a1; mi = lane + 32;
                }
#pragma unroll
                for (int off = 16; off > 0; off >>= 1) {
                    float ov = __shfl_xor_sync(0xffffffffu, mv, off);
                    int   oi = __shfl_xor_sync(0xffffffffu, mi, off);
                    if (ov > mv || (ov == mv && oi < mi)) { mv = ov; mi = oi; }
                }
                tv[t] = mv;
                ti[t] = mi;
                if (mi == lane)      used0 = true;
                if (mi == lane + 32) used1 = true;
            }

            float mx = tv[0];
            float s = 0.0f;
            float ev[K_TOP];
#pragma unroll
            for (int t = 0; t < K_TOP; ++t) { ev[t] = expf(tv[t] - mx); s += ev[t]; }
            float inv = 1.0f / s;

            float w0 = 0.0f, w1 = 0.0f;
#pragma unroll
            for (int t = 0; t < K_TOP; ++t) {
                float e = ev[t] * inv;
                if (ti[t] == lane)      w0 = e;
                if (ti[t] == lane + 32) w1 = e;
            }
            out_w[(size_t)r * E_SZ + lane]      = w0;
            out_w[(size_t)r * E_SZ + lane + 32] = w1;
        }
    }
}

// ---------------------------------------------------------------------------
extern "C" void kernel_launch(void* const* d_in, const int* in_sizes, int n_in,
                              void* d_out, int out_size) {
    const float* r_pooled    = (const float*)d_in[0];
    const float* step_frac   = (const float*)d_in[1];
    const float* hidden_norm = (const float*)d_in[2];
    const float* confidence  = (const float*)d_in[3];
    const float* W1          = (const float*)d_in[4];
    const float* b1          = (const float*)d_in[5];
    const float* W2          = (const float*)d_in[6];
    const float* b2          = (const float*)d_in[7];
    float* out = (float*)d_out;

    cudaFuncSetAttribute(fused_router_kernel,
                         cudaFuncAttributeMaxDynamicSharedMemorySize,
                         SMEM_U32 * 4);

    prep_b_kernel<<<D_SZ * H_SZ / (256 * 4), 256>>>(W1);
    fused_router_kernel<<<B_SZ / 128, 512, SMEM_U32 * 4>>>(
        r_pooled, W1, b1, step_frac, hidden_norm, confidence, W2, b2, out);
}

// round 15
// speedup vs baseline: 2.1599x; 1.1032x over previous
#include <cuda_runtime.h>
#include <cuda_fp16.h>
#include <math.h>
#include <stdint.h>

#define B_SZ 16384
#define D_SZ 4096
#define H_SZ 128
#define E_SZ 64
#define K_TOP 8

// Pre-split W1 as packed fp16 pairs, [k][n] layout, 2 MB each.
// cb1 = half2(b1*64, b1/64), cb2 = half2(e_b*64, e_b/64), b = b1 + e_b.
__device__ uint32_t g_bc1[D_SZ * H_SZ];
__device__ uint32_t g_bc2[D_SZ * H_SZ];

__device__ __forceinline__ uint32_t smem_u32(const void* p) {
    uint32_t a;
    asm("{ .reg .u64 t; cvta.to.shared.u64 t, %1; cvt.u32.u64 %0, t; }"
        : "=r"(a) : "l"(p));
    return a;
}
// A pack: a = a1 + e_a; ca = half2(a1/64, e_a*64)
__device__ __forceinline__ uint32_t pack_a(float a) {
    __half h1 = __float2half_rn(a);
    float f1 = __half2float(h1);
    float e  = a - f1;
    __half2 p = __floats2half2_rn(f1 * 0.015625f, e * 64.0f);
    return *(uint32_t*)&p;
}

#define CP_ASYNC16(dst_u32, src_ptr)                                          \
    asm volatile("cp.async.cg.shared.global [%0], [%1], 16;"                  \
                 :: "r"(dst_u32), "l"(src_ptr))
#define CP_ASYNC_COMMIT() asm volatile("cp.async.commit_group;" ::: "memory")
#define CP_ASYNC_WAIT0()  asm volatile("cp.async.wait_group 0;" ::: "memory")

#define MMA_F16(C, A0, A1, A2, A3, B0, B1)                                    \
    asm volatile(                                                             \
        "mma.sync.aligned.m16n8k16.row.col.f32.f16.f16.f32 "                  \
        "{%0,%1,%2,%3}, {%4,%5,%6,%7}, {%8,%9}, {%0,%1,%2,%3};"               \
        : "+f"(C[0]), "+f"(C[1]), "+f"(C[2]), "+f"(C[3])                      \
        : "r"(A0), "r"(A1), "r"(A2), "r"(A3), "r"(B0), "r"(B1))

// ---------------------------------------------------------------------------
// Prep: W1 -> packed fp16 head/residual pair arrays.
// ---------------------------------------------------------------------------
__global__ __launch_bounds__(256)
void prep_b_kernel(const float* __restrict__ W1) {
    int idx = (blockIdx.x * 256 + threadIdx.x) * 4;
    float4 v = *(const float4*)&W1[idx];
    uint4 c1, c2;
    const float* pv = &v.x;
    uint32_t* p1 = &c1.x;
    uint32_t* p2 = &c2.x;
#pragma unroll
    for (int j = 0; j < 4; ++j) {
        __half h1 = __float2half_rn(pv[j]);
        float f1 = __half2float(h1);
        float e  = pv[j] - f1;
        __half2 a = __floats2half2_rn(f1 * 64.0f, f1 * 0.015625f);
        __half2 b = __floats2half2_rn(e * 64.0f, e * 0.015625f);
        p1[j] = *(uint32_t*)&a;
        p2[j] = *(uint32_t*)&b;
    }
    *(uint4*)&g_bc1[idx] = c1;
    *(uint4*)&g_bc2[idx] = c2;
}

// ---------------------------------------------------------------------------
// Fused kernel: h = silu(features @ W1 + b1), then router epilogue.
// BM=128, BN=128(H), BK=32. 512 threads = 16 warps (4m x 4n), warp tile 32x32.
// Per k8 step per (mi,ni): 2 fp16 k16 MMAs sharing one A fragment:
//   MMA(ca,cb2) + MMA(ca,cb1) = (a1+ea)(b1+eb) = a*b  (fp32 accumulate).
// ---------------------------------------------------------------------------
#define BK 32
#define AS_STRIDE 36   // bank(4g+tg) conflict-free for frag loads
#define BS_STRIDE 136  // bank(8tg+g) conflict-free

#define A_STG   (128 * AS_STRIDE)        // 4608 u32 (Ca packed pairs)
#define B_STG   (BK * BS_STRIDE)         // 4352 u32 per B array
#define STG     (A_STG + 2 * B_STG)      // 13312 u32 per stage
#define OFF_CA(s) ((s) * STG + 0)
#define OFF_B1(s) ((s) * STG + A_STG)
#define OFF_B2(s) ((s) * STG + A_STG + B_STG)
#define SMEM_U32  (2 * STG)              // 26624 u32 = 106496 bytes

#define HS_STRIDE 132                    // hs overlay [0 .. 16896)
#define OFF_WS2   16896                  // ws2 overlay [16896 .. 25088)

__global__ __launch_bounds__(512)
void fused_router_kernel(const float* __restrict__ A,     // (B, D)
                         const float* __restrict__ W1,    // (D+3, H)
                         const float* __restrict__ b1,    // (H)
                         const float* __restrict__ stepp, // (1)
                         const float* __restrict__ hn,    // (B)
                         const float* __restrict__ conf,  // (B)
                         const float* __restrict__ W2,    // (H, E)
                         const float* __restrict__ b2,    // (E)
                         float* __restrict__ out)
{
    extern __shared__ uint32_t smem[];
    const uint32_t sb = smem_u32(smem);

    const int tid  = threadIdx.x;
    const int lane = tid & 31;
    const int w    = tid >> 5;
    const int wm   = (w & 3) * 32;   // 4 warps in m
    const int wn   = (w >> 2) * 32;  // 4 warps in n
    const int g    = lane >> 2;
    const int tg   = lane & 3;
    const int m0   = blockIdx.x * 128;

    // B copy mapping: f=i*512+tid; brow=f>>5, bc=(f&31)*4
    const int brow0 = tid >> 5;
    const int bc0   = (tid & 31) * 4;
    const int brow1 = (512 + tid) >> 5;
    const uint32_t bdst0 = brow0 * BS_STRIDE + bc0;
    const uint32_t bdst1 = brow1 * BS_STRIDE + bc0;

    float acc[2][4][4];
    float sum[2][4][4];
#pragma unroll
    for (int mi = 0; mi < 2; ++mi)
#pragma unroll
        for (int ni = 0; ni < 4; ++ni)
#pragma unroll
            for (int c = 0; c < 4; ++c) { acc[mi][ni][c] = 0.0f; sum[mi][ni][c] = 0.0f; }

    // A writer mapping: f=i*512+tid, arow=f>>3, ak=(f&7)*4
    float4 pa[2];
#pragma unroll
    for (int i = 0; i < 2; ++i) {
        int f = i * 512 + tid;
        pa[i] = *(const float4*)&A[(size_t)(m0 + (f >> 3)) * D_SZ + (f & 7) * 4];
    }

    // prologue: stage 0
    CP_ASYNC16(sb + (OFF_B1(0) + bdst0) * 4, &g_bc1[(size_t)brow0 * H_SZ + bc0]);
    CP_ASYNC16(sb + (OFF_B1(0) + bdst1) * 4, &g_bc1[(size_t)brow1 * H_SZ + bc0]);
    CP_ASYNC16(sb + (OFF_B2(0) + bdst0) * 4, &g_bc2[(size_t)brow0 * H_SZ + bc0]);
    CP_ASYNC16(sb + (OFF_B2(0) + bdst1) * 4, &g_bc2[(size_t)brow1 * H_SZ + bc0]);
    CP_ASYNC_COMMIT();
#pragma unroll
    for (int i = 0; i < 2; ++i) {
        int f = i * 512 + tid;
        uint4 c4;
        c4.x = pack_a(pa[i].x); c4.y = pack_a(pa[i].y);
        c4.z = pack_a(pa[i].z); c4.w = pack_a(pa[i].w);
        int ao = (f >> 3) * AS_STRIDE + (f & 7) * 4;
        *(uint4*)&smem[OFF_CA(0) + ao] = c4;
    }
    CP_ASYNC_WAIT0();

    const int NIT = D_SZ / BK;   // 128
    for (int it = 0; it < NIT; ++it) {
        __syncthreads();
        const int cur = it & 1;
        const bool pre = (it + 1 < NIT);

        if (pre) {
            const int nxt = cur ^ 1;
            const int k0 = (it + 1) * BK;
            CP_ASYNC16(sb + (OFF_B1(nxt) + bdst0) * 4, &g_bc1[(size_t)(k0 + brow0) * H_SZ + bc0]);
            CP_ASYNC16(sb + (OFF_B1(nxt) + bdst1) * 4, &g_bc1[(size_t)(k0 + brow1) * H_SZ + bc0]);
            CP_ASYNC16(sb + (OFF_B2(nxt) + bdst0) * 4, &g_bc2[(size_t)(k0 + brow0) * H_SZ + bc0]);
            CP_ASYNC16(sb + (OFF_B2(nxt) + bdst1) * 4, &g_bc2[(size_t)(k0 + brow1) * H_SZ + bc0]);
            CP_ASYNC_COMMIT();
#pragma unroll
            for (int i = 0; i < 2; ++i) {
                int f = i * 512 + tid;
                pa[i] = *(const float4*)&A[(size_t)(m0 + (f >> 3)) * D_SZ + k0 + (f & 7) * 4];
            }
        }

        const uint32_t* Ca = &smem[OFF_CA(cur)];
        const uint32_t* B1s = &smem[OFF_B1(cur)];
        const uint32_t* B2s = &smem[OFF_B2(cur)];

#pragma unroll
        for (int ks = 0; ks < 4; ++ks) {
            uint32_t ca[2][4], c1[4][2], c2[4][2];
#pragma unroll
            for (int mi = 0; mi < 2; ++mi) {
                int base = (wm + mi * 16 + g) * AS_STRIDE + ks * 8 + tg;
                ca[mi][0] = Ca[base];                     // row g,   vk 2tg
                ca[mi][1] = Ca[base + 8 * AS_STRIDE];     // row g+8, vk 2tg
                ca[mi][2] = Ca[base + 4];                 // row g,   vk 2tg+8
                ca[mi][3] = Ca[base + 8 * AS_STRIDE + 4]; // row g+8, vk 2tg+8
            }
#pragma unroll
            for (int ni = 0; ni < 4; ++ni) {
                int base = (ks * 8 + tg) * BS_STRIDE + wn + ni * 8 + g;
                c1[ni][0] = B1s[base];
                c1[ni][1] = B1s[base + 4 * BS_STRIDE];
                c2[ni][0] = B2s[base];
                c2[ni][1] = B2s[base + 4 * BS_STRIDE];
            }
#pragma unroll
            for (int mi = 0; mi < 2; ++mi)
#pragma unroll
                for (int ni = 0; ni < 4; ++ni) {
                    float* c = acc[mi][ni];
                    // small terms first: a1*eb + ea*eb
                    MMA_F16(c, ca[mi][0], ca[mi][1], ca[mi][2], ca[mi][3],
                            c2[ni][0], c2[ni][1]);
                    // dominant: a1*b1 + ea*b1
                    MMA_F16(c, ca[mi][0], ca[mi][1], ca[mi][2], ca[mi][3],
                            c1[ni][0], c1[ni][1]);
                }
        }

        if (pre) {   // pack + store A into stage nxt
            const int nxt = cur ^ 1;
#pragma unroll
            for (int i = 0; i < 2; ++i) {
                int f = i * 512 + tid;
                uint4 c4;
                c4.x = pack_a(pa[i].x); c4.y = pack_a(pa[i].y);
                c4.z = pack_a(pa[i].z); c4.w = pack_a(pa[i].w);
                int ao = (f >> 3) * AS_STRIDE + (f & 7) * 4;
                *(uint4*)&smem[OFF_CA(nxt) + ao] = c4;
            }
        }

        // drain RZ accumulators into RN sums every 2 iters (64 k), validated
        if ((it & 1) == 1) {
#pragma unroll
            for (int mi = 0; mi < 2; ++mi)
#pragma unroll
                for (int ni = 0; ni < 4; ++ni)
#pragma unroll
                    for (int c = 0; c < 4; ++c) {
                        sum[mi][ni][c] += acc[mi][ni][c];
                        acc[mi][ni][c] = 0.0f;
                    }
        }

        if (pre) CP_ASYNC_WAIT0();
    }

    // hs overlay spans beyond stage 0 now: must wait for ALL warps' MMA reads.
    __syncthreads();

    // ---- epilogue stage A: rank-1 terms, bias, silu -> hs in smem ----
    float* hs = (float*)smem;                       // [128][HS_STRIDE]
    {
        const float step = stepp[0];
        float colc[4][2], w2r[4][2], w3r[4][2];
#pragma unroll
        for (int ni = 0; ni < 4; ++ni)
#pragma unroll
            for (int j = 0; j < 2; ++j) {
                int col = wn + ni * 8 + 2 * tg + j;
                colc[ni][j] = fmaf(step, W1[(size_t)D_SZ * H_SZ + col], b1[col]);
                w2r[ni][j]  = W1[(size_t)(D_SZ + 1) * H_SZ + col];
                w3r[ni][j]  = W1[(size_t)(D_SZ + 2) * H_SZ + col];
            }
#pragma unroll
        for (int mi = 0; mi < 2; ++mi) {
            int lr0 = wm + mi * 16 + g;
            int lr1 = lr0 + 8;
            float hv0 = hn[m0 + lr0], cv0 = conf[m0 + lr0];
            float hv1 = hn[m0 + lr1], cv1 = conf[m0 + lr1];
#pragma unroll
            for (int ni = 0; ni < 4; ++ni) {
                int col0 = wn + ni * 8 + 2 * tg;
                float x00 = sum[mi][ni][0] + colc[ni][0] + hv0 * w2r[ni][0] + cv0 * w3r[ni][0];
                float x01 = sum[mi][ni][1] + colc[ni][1] + hv0 * w2r[ni][1] + cv0 * w3r[ni][1];
                float x10 = sum[mi][ni][2] + colc[ni][0] + hv1 * w2r[ni][0] + cv1 * w3r[ni][0];
                float x11 = sum[mi][ni][3] + colc[ni][1] + hv1 * w2r[ni][1] + cv1 * w3r[ni][1];
                float2 s0, s1;
                s0.x = x00 / (1.0f + expf(-x00));
                s0.y = x01 / (1.0f + expf(-x01));
                s1.x = x10 / (1.0f + expf(-x10));
                s1.y = x11 / (1.0f + expf(-x11));
                *(float2*)&hs[lr0 * HS_STRIDE + col0] = s0;
                *(float2*)&hs[lr1 * HS_STRIDE + col0] = s1;
            }
        }
    }

    // ---- epilogue stage B: load W2 pair-permuted (disjoint smem region) ----
    float2* ws2 = (float2*)&smem[OFF_WS2];          // [H_SZ][32] pairs (e, e+32)
    for (int i = tid; i < H_SZ * 32; i += 512) {
        int k = i >> 5, j = i & 31;
        ws2[i] = make_float2(W2[k * E_SZ + j], W2[k * E_SZ + j + 32]);
    }
    __syncthreads();

    // ---- epilogue stage C: per-warp GEMV + top-8 + softmax for 8 rows ----
    {
        const float bz0 = b2[lane];
        const float bz1 = b2[lane + 32];
        float acc0[8], acc1[8];
#pragma unroll
        for (int rr = 0; rr < 8; ++rr) { acc0[rr] = bz0; acc1[rr] = bz1; }

        const float* hrow = &hs[(w * 8) * HS_STRIDE];
        for (int k = 0; k < H_SZ; ++k) {
            float2 wv = ws2[k * 32 + lane];
#pragma unroll
            for (int rr = 0; rr < 8; ++rr) {
                float hv = hrow[rr * HS_STRIDE + k];
                acc0[rr] = fmaf(hv, wv.x, acc0[rr]);
                acc1[rr] = fmaf(hv, wv.y, acc1[rr]);
            }
        }

        float* out_w = out;
        float* out_l = out + (size_t)B_SZ * E_SZ;
#pragma unroll
        for (int rr = 0; rr < 8; ++rr) {
            const int r = m0 + w * 8 + rr;
            const float a0 = acc0[rr], a1 = acc1[rr];
            out_l[(size_t)r * E_SZ + lane]      = a0;
            out_l[(size_t)r * E_SZ + lane + 32] = a1;

            bool used0 = false, used1 = false;
            float tv[K_TOP];
            int   ti[K_TOP];
#pragma unroll
            for (int t = 0; t < K_TOP; ++t) {
                float mv = -3.402823466e38f;
                int   mi = 1 << 30;
                if (!used0) { mv = a0; mi = lane; }
                if (!used1 && (a1 > mv || (a1 == mv && lane + 32 < mi))) {
                    mv = a1; mi = lane + 32;
                }
#pragma unroll
                for (int off = 16; off > 0; off >>= 1) {
                    float ov = __shfl_xor_sync(0xffffffffu, mv, off);
                    int   oi = __shfl_xor_sync(0xffffffffu, mi, off);
                    if (ov > mv || (ov == mv && oi < mi)) { mv = ov; mi = oi; }
                }
                tv[t] = mv;
                ti[t] = mi;
                if (mi == lane)      used0 = true;
                if (mi == lane + 32) used1 = true;
            }

            float mx = tv[0];
            float s = 0.0f;
            float ev[K_TOP];
#pragma unroll
            for (int t = 0; t < K_TOP; ++t) { ev[t] = expf(tv[t] - mx); s += ev[t]; }
            float inv = 1.0f / s;

            float w0 = 0.0f, w1 = 0.0f;
#pragma unroll
            for (int t = 0; t < K_TOP; ++t) {
                float e = ev[t] * inv;
                if (ti[t] == lane)      w0 = e;
                if (ti[t] == lane + 32) w1 = e;
            }
            out_w[(size_t)r * E_SZ + lane]      = w0;
            out_w[(size_t)r * E_SZ + lane + 32] = w1;
        }
    }
}

// ---------------------------------------------------------------------------
extern "C" void kernel_launch(void* const* d_in, const int* in_sizes, int n_in,
                              void* d_out, int out_size) {
    const float* r_pooled    = (const float*)d_in[0];
    const float* step_frac   = (const float*)d_in[1];
    const float* hidden_norm = (const float*)d_in[2];
    const float* confidence  = (const float*)d_in[3];
    const float* W1          = (const float*)d_in[4];
    const float* b1          = (const float*)d_in[5];
    const float* W2          = (const float*)d_in[6];
    const float* b2          = (const float*)d_in[7];
    float* out = (float*)d_out;

    cudaFuncSetAttribute(fused_router_kernel,
                         cudaFuncAttributeMaxDynamicSharedMemorySize,
                         SMEM_U32 * 4);

    prep_b_kernel<<<D_SZ * H_SZ / (256 * 4), 256>>>(W1);
    fused_router_kernel<<<B_SZ / 128, 512, SMEM_U32 * 4>>>(
        r_pooled, W1, b1, step_frac, hidden_norm, confidence, W2, b2, out);
}

// round 17
// speedup vs baseline: 2.2322x; 1.0335x over previous
#include <cuda_runtime.h>
#include <cuda_fp16.h>
#include <math.h>
#include <stdint.h>

#define B_SZ 16384
#define D_SZ 4096
#define H_SZ 128
#define E_SZ 64
#define K_TOP 8

// Pre-split W1 as packed fp16 pairs, TRANSPOSED [n][k] layout, 2 MB each.
// c1 = half2(b1*64, b1/64), c2 = half2(e*64, e/64), b = b1 + e.
__device__ uint32_t g_bc1[H_SZ * D_SZ];
__device__ uint32_t g_bc2[H_SZ * D_SZ];

__device__ __forceinline__ uint32_t smem_u32(const void* p) {
    uint32_t a;
    asm("{ .reg .u64 t; cvta.to.shared.u64 t, %1; cvt.u32.u64 %0, t; }"
        : "=r"(a) : "l"(p));
    return a;
}
// A pack: a = a1 + e_a; ca = half2(a1/64, e_a*64)
__device__ __forceinline__ uint32_t pack_a(float a) {
    __half h1 = __float2half_rn(a);
    float f1 = __half2float(h1);
    float e  = a - f1;
    __half2 p = __floats2half2_rn(f1 * 0.015625f, e * 64.0f);
    return *(uint32_t*)&p;
}

#define CP_ASYNC16(dst_u32, src_ptr)                                          \
    asm volatile("cp.async.cg.shared.global [%0], [%1], 16;"                  \
                 :: "r"(dst_u32), "l"(src_ptr))
#define CP_ASYNC_COMMIT() asm volatile("cp.async.commit_group;" ::: "memory")
#define CP_ASYNC_WAIT0()  asm volatile("cp.async.wait_group 0;" ::: "memory")

#define MMA_F16(C, A0, A1, A2, A3, B0, B1)                                    \
    asm volatile(                                                             \
        "mma.sync.aligned.m16n8k16.row.col.f32.f16.f16.f32 "                  \
        "{%0,%1,%2,%3}, {%4,%5,%6,%7}, {%8,%9}, {%0,%1,%2,%3};"               \
        : "+f"(C[0]), "+f"(C[1]), "+f"(C[2]), "+f"(C[3])                      \
        : "r"(A0), "r"(A1), "r"(A2), "r"(A3), "r"(B0), "r"(B1))

#define LDSM4(R0, R1, R2, R3, addr)                                           \
    asm volatile("ldmatrix.sync.aligned.m8n8.x4.shared.b16 {%0,%1,%2,%3}, [%4];" \
                 : "=r"(R0), "=r"(R1), "=r"(R2), "=r"(R3) : "r"(addr))

// ---------------------------------------------------------------------------
// Prep: W1[k][n] -> transposed packed fp16 head/residual arrays [n][k].
// ---------------------------------------------------------------------------
__global__ __launch_bounds__(256)
void prep_b_kernel(const float* __restrict__ W1) {
    __shared__ float ts[32][33];
    const int tx = threadIdx.x & 31;
    const int ty = threadIdx.x >> 5;          // 0..7
    const int k0 = blockIdx.x * 32;
    const int n0 = blockIdx.y * 32;
#pragma unroll
    for (int j = 0; j < 4; ++j)
        ts[ty + j * 8][tx] = W1[(size_t)(k0 + ty + j * 8) * H_SZ + n0 + tx];
    __syncthreads();
#pragma unroll
    for (int j = 0; j < 4; ++j) {
        int n = n0 + ty + j * 8;
        int k = k0 + tx;
        float v = ts[tx][ty + j * 8];
        __half h1 = __float2half_rn(v);
        float f1 = __half2float(h1);
        float e  = v - f1;
        __half2 a = __floats2half2_rn(f1 * 64.0f, f1 * 0.015625f);
        __half2 b = __floats2half2_rn(e * 64.0f, e * 0.015625f);
        g_bc1[(size_t)n * D_SZ + k] = *(uint32_t*)&a;
        g_bc2[(size_t)n * D_SZ + k] = *(uint32_t*)&b;
    }
}

// ---------------------------------------------------------------------------
// Fused kernel: h = silu(features @ W1 + b1), then router epilogue.
// BM=128, BN=128(H), BK=32. 512 threads = 16 warps (4m x 4n), warp tile 32x32.
// Fragments via ldmatrix.x4: 24 LDSM/iter/thread vs 96 scalar LDS.
// ---------------------------------------------------------------------------
#define BK 32
#define AS_STRIDE 36   // rows stride 36 u32: 8-row LDSM phases conflict-free
#define BS_STRIDE 36   // B now [n][k]: 128 rows x (32 data + 4 pad) u32

#define A_STG   (128 * AS_STRIDE)        // 4608 u32 (Ca packed pairs)
#define B_STG   (128 * BS_STRIDE)        // 4608 u32 per B array
#define STG     (A_STG + 2 * B_STG)      // 13824 u32 per stage
#define OFF_CA(s) ((s) * STG + 0)
#define OFF_B1(s) ((s) * STG + A_STG)
#define SMEM_U32  (2 * STG)              // 27648 u32 = 110592 bytes

#define HS_STRIDE 132                    // hs overlay [0 .. 16896)
#define OFF_WS2   16896                  // ws2 overlay [16896 .. 20992)

__global__ __launch_bounds__(512)
void fused_router_kernel(const float* __restrict__ A,     // (B, D)
                         const float* __restrict__ W1,    // (D+3, H)
                         const float* __restrict__ b1,    // (H)
                         const float* __restrict__ stepp, // (1)
                         const float* __restrict__ hn,    // (B)
                         const float* __restrict__ conf,  // (B)
                         const float* __restrict__ W2,    // (H, E)
                         const float* __restrict__ b2,    // (E)
                         float* __restrict__ out)
{
    extern __shared__ __align__(16) uint32_t smem[];
    const uint32_t sb = smem_u32(smem);

    const int tid  = threadIdx.x;
    const int lane = tid & 31;
    const int w    = tid >> 5;
    const int wm   = (w & 3) * 32;   // 4 warps in m
    const int wn   = (w >> 2) * 32;  // 4 warps in n
    const int g    = lane >> 2;
    const int tg   = lane & 3;
    const int m0   = blockIdx.x * 128;

    // ldmatrix per-lane address parts (u32 units)
    // A (x4): q=lane>>3: m0:rows+0 k+0 | m1:rows+8 k+0 | m2:rows+0 k+4 | m3:rows+8 k+4
    const uint32_t aln = ((lane & 7) + ((lane >> 3) & 1) * 8) * AS_STRIDE
                       + ((lane >> 4) & 1) * 4;
    // B (x4): q0: B1 k+0 | q1: B1 k+4 | q2: B2 k+0 | q3: B2 k+4 ; rows = n
    const int bq = lane >> 3;
    const uint32_t bln = (lane & 7) * BS_STRIDE + (bq & 1) * 4
                       + (bq >> 1) * B_STG;

    // B cp.async mapping: chunk i*512+tid: row = i*64 + (tid>>3), c16 = tid&7
    const int brow = tid >> 3;
    const int bcc  = (tid & 7) * 4;
    const uint32_t bdst0 = brow * BS_STRIDE + bcc;
    const uint32_t bdst1 = (64 + brow) * BS_STRIDE + bcc;

    float acc[2][4][4];
    float sum[2][4][4];
#pragma unroll
    for (int mi = 0; mi < 2; ++mi)
#pragma unroll
        for (int ni = 0; ni < 4; ++ni)
#pragma unroll
            for (int c = 0; c < 4; ++c) { acc[mi][ni][c] = 0.0f; sum[mi][ni][c] = 0.0f; }

    // A writer mapping: f=i*512+tid, arow=f>>3, ak=(f&7)*4
    float4 pa[2];
#pragma unroll
    for (int i = 0; i < 2; ++i) {
        int f = i * 512 + tid;
        pa[i] = *(const float4*)&A[(size_t)(m0 + (f >> 3)) * D_SZ + (f & 7) * 4];
    }

    // prologue: stage 0
    CP_ASYNC16(sb + (OFF_B1(0) + bdst0) * 4,         &g_bc1[(size_t)brow * D_SZ + bcc]);
    CP_ASYNC16(sb + (OFF_B1(0) + bdst1) * 4,         &g_bc1[(size_t)(64 + brow) * D_SZ + bcc]);
    CP_ASYNC16(sb + (OFF_B1(0) + B_STG + bdst0) * 4, &g_bc2[(size_t)brow * D_SZ + bcc]);
    CP_ASYNC16(sb + (OFF_B1(0) + B_STG + bdst1) * 4, &g_bc2[(size_t)(64 + brow) * D_SZ + bcc]);
    CP_ASYNC_COMMIT();
#pragma unroll
    for (int i = 0; i < 2; ++i) {
        int f = i * 512 + tid;
        uint4 c4;
        c4.x = pack_a(pa[i].x); c4.y = pack_a(pa[i].y);
        c4.z = pack_a(pa[i].z); c4.w = pack_a(pa[i].w);
        int ao = (f >> 3) * AS_STRIDE + (f & 7) * 4;
        *(uint4*)&smem[OFF_CA(0) + ao] = c4;
    }
    CP_ASYNC_WAIT0();

    const int NIT = D_SZ / BK;   // 128
    for (int it = 0; it < NIT; ++it) {
        __syncthreads();
        const int cur = it & 1;
        const bool pre = (it + 1 < NIT);

        if (pre) {
            const int nxt = cur ^ 1;
            const int k0 = (it + 1) * BK;
            CP_ASYNC16(sb + (OFF_B1(nxt) + bdst0) * 4,         &g_bc1[(size_t)brow * D_SZ + k0 + bcc]);
            CP_ASYNC16(sb + (OFF_B1(nxt) + bdst1) * 4,         &g_bc1[(size_t)(64 + brow) * D_SZ + k0 + bcc]);
            CP_ASYNC16(sb + (OFF_B1(nxt) + B_STG + bdst0) * 4, &g_bc2[(size_t)brow * D_SZ + k0 + bcc]);
            CP_ASYNC16(sb + (OFF_B1(nxt) + B_STG + bdst1) * 4, &g_bc2[(size_t)(64 + brow) * D_SZ + k0 + bcc]);
            CP_ASYNC_COMMIT();
#pragma unroll
            for (int i = 0; i < 2; ++i) {
                int f = i * 512 + tid;
                pa[i] = *(const float4*)&A[(size_t)(m0 + (f >> 3)) * D_SZ + k0 + (f & 7) * 4];
            }
        }

        const uint32_t aBase = sb + (OFF_CA(cur) + wm * AS_STRIDE + aln) * 4;
        const uint32_t bBase = sb + (OFF_B1(cur) + wn * BS_STRIDE + bln) * 4;

#pragma unroll
        for (int ks = 0; ks < 4; ++ks) {
            uint32_t ca[2][4], c1[4][2], c2[4][2];
#pragma unroll
            for (int mi = 0; mi < 2; ++mi)
                LDSM4(ca[mi][0], ca[mi][1], ca[mi][2], ca[mi][3],
                      aBase + (mi * (16 * AS_STRIDE) + ks * 8) * 4);
#pragma unroll
            for (int ni = 0; ni < 4; ++ni)
                LDSM4(c1[ni][0], c1[ni][1], c2[ni][0], c2[ni][1],
                      bBase + (ni * (8 * BS_STRIDE) + ks * 8) * 4);
#pragma unroll
            for (int mi = 0; mi < 2; ++mi)
#pragma unroll
                for (int ni = 0; ni < 4; ++ni) {
                    float* c = acc[mi][ni];
                    // small terms first: a1*eb + ea*eb
                    MMA_F16(c, ca[mi][0], ca[mi][1], ca[mi][2], ca[mi][3],
                            c2[ni][0], c2[ni][1]);
                    // dominant: a1*b1 + ea*b1
                    MMA_F16(c, ca[mi][0], ca[mi][1], ca[mi][2], ca[mi][3],
                            c1[ni][0], c1[ni][1]);
                }
        }

        if (pre) {   // pack + store A into stage nxt
            const int nxt = cur ^ 1;
#pragma unroll
            for (int i = 0; i < 2; ++i) {
                int f = i * 512 + tid;
                uint4 c4;
                c4.x = pack_a(pa[i].x); c4.y = pack_a(pa[i].y);
                c4.z = pack_a(pa[i].z); c4.w = pack_a(pa[i].w);
                int ao = (f >> 3) * AS_STRIDE + (f & 7) * 4;
                *(uint4*)&smem[OFF_CA(nxt) + ao] = c4;
            }
        }

        // drain RZ accumulators into RN sums every 2 iters (64 k), validated
        if ((it & 1) == 1) {
#pragma unroll
            for (int mi = 0; mi < 2; ++mi)
#pragma unroll
                for (int ni = 0; ni < 4; ++ni)
#pragma unroll
                    for (int c = 0; c < 4; ++c) {
                        sum[mi][ni][c] += acc[mi][ni][c];
                        acc[mi][ni][c] = 0.0f;
                    }
        }

        if (pre) CP_ASYNC_WAIT0();
    }

    // hs overlay spans beyond stage 0: wait for ALL warps' MMA reads.
    __syncthreads();

    // ---- epilogue stage A: rank-1 terms, bias, silu -> hs in smem ----
    float* hs = (float*)smem;                       // [128][HS_STRIDE]
    {
        const float step = stepp[0];
        float colc[4][2], w2r[4][2], w3r[4][2];
#pragma unroll
        for (int ni = 0; ni < 4; ++ni)
#pragma unroll
            for (int j = 0; j < 2; ++j) {
                int col = wn + ni * 8 + 2 * tg + j;
                colc[ni][j] = fmaf(step, W1[(size_t)D_SZ * H_SZ + col], b1[col]);
                w2r[ni][j]  = W1[(size_t)(D_SZ + 1) * H_SZ + col];
                w3r[ni][j]  = W1[(size_t)(D_SZ + 2) * H_SZ + col];
            }
#pragma unroll
        for (int mi = 0; mi < 2; ++mi) {
            int lr0 = wm + mi * 16 + g;
            int lr1 = lr0 + 8;
            float hv0 = hn[m0 + lr0], cv0 = conf[m0 + lr0];
            float hv1 = hn[m0 + lr1], cv1 = conf[m0 + lr1];
#pragma unroll
            for (int ni = 0; ni < 4; ++ni) {
                int col0 = wn + ni * 8 + 2 * tg;
                float x00 = sum[mi][ni][0] + colc[ni][0] + hv0 * w2r[ni][0] + cv0 * w3r[ni][0];
                float x01 = sum[mi][ni][1] + colc[ni][1] + hv0 * w2r[ni][1] + cv0 * w3r[ni][1];
                float x10 = sum[mi][ni][2] + colc[ni][0] + hv1 * w2r[ni][0] + cv1 * w3r[ni][0];
                float x11 = sum[mi][ni][3] + colc[ni][1] + hv1 * w2r[ni][1] + cv1 * w3r[ni][1];
                float2 s0, s1;
                s0.x = x00 / (1.0f + expf(-x00));
                s0.y = x01 / (1.0f + expf(-x01));
                s1.x = x10 / (1.0f + expf(-x10));
                s1.y = x11 / (1.0f + expf(-x11));
                *(float2*)&hs[lr0 * HS_STRIDE + col0] = s0;
                *(float2*)&hs[lr1 * HS_STRIDE + col0] = s1;
            }
        }
    }

    // ---- epilogue stage B: load W2 pair-permuted (disjoint smem region) ----
    float2* ws2 = (float2*)&smem[OFF_WS2];          // [H_SZ][32] pairs (e, e+32)
    for (int i = tid; i < H_SZ * 32; i += 512) {
        int k = i >> 5, j = i & 31;
        ws2[i] = make_float2(W2[k * E_SZ + j], W2[k * E_SZ + j + 32]);
    }
    __syncthreads();

    // ---- epilogue stage C: per-warp GEMV + top-8 + softmax for 8 rows ----
    {
        const float bz0 = b2[lane];
        const float bz1 = b2[lane + 32];
        float acc0[8], acc1[8];
#pragma unroll
        for (int rr = 0; rr < 8; ++rr) { acc0[rr] = bz0; acc1[rr] = bz1; }

        const float* hrow = &hs[(w * 8) * HS_STRIDE];
        for (int k = 0; k < H_SZ; ++k) {
            float2 wv = ws2[k * 32 + lane];
#pragma unroll
            for (int rr = 0; rr < 8; ++rr) {
                float hv = hrow[rr * HS_STRIDE + k];
                acc0[rr] = fmaf(hv, wv.x, acc0[rr]);
                acc1[rr] = fmaf(hv, wv.y, acc1[rr]);
            }
        }

        float* out_w = out;
        float* out_l = out + (size_t)B_SZ * E_SZ;
#pragma unroll
        for (int rr = 0; rr < 8; ++rr) {
            const int r = m0 + w * 8 + rr;
            const float a0 = acc0[rr], a1 = acc1[rr];
            out_l[(size_t)r * E_SZ + lane]      = a0;
            out_l[(size_t)r * E_SZ + lane + 32] = a1;

            bool used0 = false, used1 = false;
            float tv[K_TOP];
            int   ti[K_TOP];
#pragma unroll
            for (int t = 0; t < K_TOP; ++t) {
                float mv = -3.402823466e38f;
                int   mi = 1 << 30;
                if (!used0) { mv = a0; mi = lane; }
                if (!used1 && (a1 > mv || (a1 == mv && lane + 32 < mi))) {
                    mv = a1; mi = lane + 32;
                }
#pragma unroll
                for (int off = 16; off > 0; off >>= 1) {
                    float ov = __shfl_xor_sync(0xffffffffu, mv, off);
                    int   oi = __shfl_xor_sync(0xffffffffu, mi, off);
                    if (ov > mv || (ov == mv && oi < mi)) { mv = ov; mi = oi; }
                }
                tv[t] = mv;
                ti[t] = mi;
                if (mi == lane)      used0 = true;
                if (mi == lane + 32) used1 = true;
            }

            float mx = tv[0];
            float s = 0.0f;
            float ev[K_TOP];
#pragma unroll
            for (int t = 0; t < K_TOP; ++t) { ev[t] = expf(tv[t] - mx); s += ev[t]; }
            float inv = 1.0f / s;

            float w0 = 0.0f, w1 = 0.0f;
#pragma unroll
            for (int t = 0; t < K_TOP; ++t) {
                float e = ev[t] * inv;
                if (ti[t] == lane)      w0 = e;
                if (ti[t] == lane + 32) w1 = e;
            }
            out_w[(size_t)r * E_SZ + lane]      = w0;
            out_w[(size_t)r * E_SZ + lane + 32] = w1;
        }
    }
}

// ---------------------------------------------------------------------------
extern "C" void kernel_launch(void* const* d_in, const int* in_sizes, int n_in,
                              void* d_out, int out_size) {
    const float* r_pooled    = (const float*)d_in[0];
    const float* step_frac   = (const float*)d_in[1];
    const float* hidden_norm = (const float*)d_in[2];
    const float* confidence  = (const float*)d_in[3];
    const float* W1          = (const float*)d_in[4];
    const float* b1          = (const float*)d_in[5];
    const float* W2          = (const float*)d_in[6];
    const float* b2          = (const float*)d_in[7];
    float* out = (float*)d_out;

    cudaFuncSetAttribute(fused_router_kernel,
                         cudaFuncAttributeMaxDynamicSharedMemorySize,
                         SMEM_U32 * 4);

    prep_b_kernel<<<dim3(D_SZ / 32, H_SZ / 32), 256>>>(W1);
    fused_router_kernel<<<B_SZ / 128, 512, SMEM_U32 * 4>>>(
        r_pooled, W1, b1, step_frac, hidden_norm, confidence, W2, b2, out);
}